// round 17
// baseline (speedup 1.0000x reference)
#include <cuda_runtime.h>

// Problem dims
#define BSZ   512
#define TT    50
#define DIN   1024
#define DH0   2048
#define DH1   1024
#define DOUTD 1024

typedef unsigned long long ULL;

// Packed dual-fp32 FMA/ADD: two independent rn-rounded fp32 ops per instr.
// Bit-identical to two scalar fmaf/fadd — used to pack two n-columns.
#define FMA2(d, a, b) \
    asm("fma.rn.f32x2 %0, %1, %2, %0;" : "+l"(d) : "l"(a), "l"(b))
#define ADD2(d, s) \
    asm("add.rn.f32x2 %0, %0, %1;" : "+l"(d) : "l"(s))

// ---------------- scratch arena ----------------
constexpr size_t CUR0_N = (size_t)BSZ * TT * DH0;   // 52,428,800 f32
constexpr size_t C0_N   = (size_t)BSZ * DH0;
constexpr size_t VEC_N  = (size_t)BSZ * DOUTD;

constexpr size_t aup(size_t x) { return (x + 1023) & ~(size_t)1023; }

constexpr size_t OFF_CUR0 = 0;
constexpr size_t OFF_C0   = aup(OFF_CUR0 + CUR0_N * 4);
constexpr size_t OFF_CUR1 = aup(OFF_C0   + C0_N * 4);
constexpr size_t OFF_C1   = aup(OFF_CUR1 + VEC_N * 4);
constexpr size_t OFF_CUR2 = aup(OFF_C1   + VEC_N * 4);
constexpr size_t OFF_C2   = aup(OFF_CUR2 + VEC_N * 4);
constexpr size_t OFF_CUR3 = aup(OFF_C2   + VEC_N * 4);
constexpr size_t OFF_C3   = aup(OFF_CUR3 + VEC_N * 4);
constexpr size_t OFF_CUR4 = aup(OFF_C3   + VEC_N * 4);
constexpr size_t SCRATCH_BYTES = aup(OFF_CUR4 + VEC_N * 4);

__device__ __align__(1024) unsigned char g_scratch[SCRATCH_BYTES];

// ---------------- output layout (out, s0, s1, s2) ----------------
constexpr size_t OUT_OFF = 0;
constexpr size_t S0_OFF  = (size_t)BSZ * DOUTD;
constexpr size_t S1_OFF  = S0_OFF + (size_t)BSZ * TT * DH0;
constexpr size_t S2_OFF  = S1_OFF + (size_t)BSZ * TT * DH1;

// ---------------- panel-ordered fp32 GEMM, f32x2-packed ----------------
// SAME per-element arithmetic as the R16 passing kernel (rel_err == 0):
//   ascending-k fma chain within KC panels, left-fold across panels.
// f32x2 packs two adjacent n-columns per instruction; each column keeps
// its own chain, so rounding is bit-identical.
// A-tile stored duplicated in smem ({a,a} pairs) so the broadcast operand
// is one LDS.128 instead of per-k register packing.
// Thread computes 4 m-rows x 8 n-cols. BN=64, BK=8, NT = 2*BM threads.
template <int BM, bool FOLD>
__global__ void gemm2_kernel(const float* __restrict__ A,
                             const float* __restrict__ B,
                             float* __restrict__ C,
                             int M, int N, int K, int KC) {
    constexpr int BN = 64, BK = 8;
    constexpr int NT  = BM * 2;
    constexpr int LDA = 2 * BM + 8;   // duplicated row + pad (16B multiple)
    constexpr int LDB = BN + 8;

    __shared__ __align__(16) float As2[BK][LDA];
    __shared__ __align__(16) float Bs[BK][LDB];

    const int tid = threadIdx.x;
    const int tx = tid & 7;          // 8 col groups (8 cols each)
    const int ty = tid >> 3;         // BM/4 row groups (4 rows each)
    const int tile_m = blockIdx.y * BM;
    const int tile_n = blockIdx.x * BN;

    ULL acc[4][4] = {};              // {0.0f,0.0f} pairs
    ULL carry[4][4] = {};            // folded panels (FOLD only)

    int next_b = KC;

    for (int k0 = 0; k0 < K; k0 += BK) {
        // A tile: NT threads, one float4 along k each, duplicated store
        {
            int m  = tid >> 1;             // 0..BM-1
            int kq = (tid & 1) * 4;        // 0 or 4
            float4 v = *reinterpret_cast<const float4*>(
                A + (size_t)(tile_m + m) * K + k0 + kq);
            float vv[4] = {v.x, v.y, v.z, v.w};
#pragma unroll
            for (int j = 0; j < 4; j++) {
                *reinterpret_cast<float2*>(&As2[kq + j][2 * m]) =
                    make_float2(vv[j], vv[j]);
            }
        }
        // B tile: 128 float4 loads (threads 0..127)
        if (tid < 128) {
            int kk = tid >> 4;             // 0..7
            int nq = (tid & 15) * 4;       // 0..60
            *reinterpret_cast<float4*>(&Bs[kk][nq]) =
                *reinterpret_cast<const float4*>(
                    B + (size_t)(k0 + kk) * N + tile_n + nq);
        }
        __syncthreads();

#pragma unroll
        for (int kk = 0; kk < BK; kk++) {  // ascending k — DO NOT REORDER
            ulonglong2 a01 = *reinterpret_cast<const ulonglong2*>(
                &As2[kk][ty * 8]);
            ulonglong2 a23 = *reinterpret_cast<const ulonglong2*>(
                &As2[kk][ty * 8 + 4]);
            ulonglong2 b01 = *reinterpret_cast<const ulonglong2*>(
                &Bs[kk][tx * 8]);
            ulonglong2 b23 = *reinterpret_cast<const ulonglong2*>(
                &Bs[kk][tx * 8 + 4]);
            ULL aa[4] = {a01.x, a01.y, a23.x, a23.y};
            ULL bb[4] = {b01.x, b01.y, b23.x, b23.y};
#pragma unroll
            for (int i = 0; i < 4; i++)
#pragma unroll
                for (int j = 0; j < 4; j++)
                    FMA2(acc[i][j], aa[i], bb[j]);
        }
        __syncthreads();

        if (FOLD) {
            int kend = k0 + BK;
            if (kend == next_b || kend == K) {   // panel fold into carry
#pragma unroll
                for (int i = 0; i < 4; i++)
#pragma unroll
                    for (int j = 0; j < 4; j++) {
                        ADD2(carry[i][j], acc[i][j]);
                        acc[i][j] = 0ULL;
                    }
                next_b += KC;
            }
        }
    }

#pragma unroll
    for (int i = 0; i < 4; i++) {
        ULL s0 = FOLD ? carry[i][0] : acc[i][0];
        ULL s1 = FOLD ? carry[i][1] : acc[i][1];
        ULL s2 = FOLD ? carry[i][2] : acc[i][2];
        ULL s3 = FOLD ? carry[i][3] : acc[i][3];
        float* cp = C + (size_t)(tile_m + ty * 4 + i) * N + tile_n + tx * 8;
        *reinterpret_cast<ulonglong2*>(cp)     = make_ulonglong2(s0, s1);
        *reinterpret_cast<ulonglong2*>(cp + 4) = make_ulonglong2(s2, s3);
    }
}

// ---------------- LIF kernels (unchanged — bit-exact proven) ----------------
__device__ __forceinline__ float lif_step(float& v, float c) {
    v = fmaf(0.25f, v, __fmul_rn(0.75f, c));
    float s = (v > 1.0f) ? 1.0f : 0.0f;
    v = __fsub_rn(v, s);
    return s;
}

__global__ void lif_seq_kernel(const float* __restrict__ cur,
                               const float* __restrict__ bias,
                               float* __restrict__ s_out,
                               float* __restrict__ cnt_out,
                               int B, int H) {
    int idx = blockIdx.x * blockDim.x + threadIdx.x;
    if (idx >= B * H) return;
    int b = idx / H, h = idx % H;
    float bb = bias[h];
    const float* cp = cur + (size_t)b * TT * H + h;
    float* sp = s_out + (size_t)b * TT * H + h;
    float v = 0.0f, cnt = 0.0f;
#pragma unroll 5
    for (int t = 0; t < TT; t++) {
        float c = __fadd_rn(cp[(size_t)t * H], bb);
        float s = lif_step(v, c);
        sp[(size_t)t * H] = s;
        cnt += s;
    }
    cnt_out[idx] = cnt;
}

template <bool WRITE_SPIKES>
__global__ void lif_const_kernel(const float* __restrict__ cur,
                                 const float* __restrict__ bias,
                                 float* __restrict__ s_out,
                                 float* __restrict__ cnt_out,
                                 int B, int H) {
    int idx = blockIdx.x * blockDim.x + threadIdx.x;
    if (idx >= B * H) return;
    int b = idx / H, h = idx % H;
    float c = __fadd_rn(cur[idx], bias[h]);
    float* sp = WRITE_SPIKES ? (s_out + (size_t)b * TT * H + h) : nullptr;
    float v = 0.0f, cnt = 0.0f;
#pragma unroll
    for (int t = 0; t < TT; t++) {
        float s = lif_step(v, c);
        if (WRITE_SPIKES) sp[(size_t)t * H] = s;
        cnt += s;
    }
    cnt_out[idx] = cnt;
}

__global__ void final_out_kernel(const float* __restrict__ cur,
                                 const float* __restrict__ bout,
                                 float* __restrict__ out) {
    int i = blockIdx.x * blockDim.x + threadIdx.x;
    if (i >= BSZ * DOUTD) return;
    out[i] = __fadd_rn(cur[i], bout[i & (DOUTD - 1)]);
}

// ---------------- launch ----------------
extern "C" void kernel_launch(void* const* d_in, const int* in_sizes, int n_in,
                              void* d_out, int out_size) {
    const float* x    = (const float*)d_in[0];
    const float* W0   = (const float*)d_in[1];
    const float* b0   = (const float*)d_in[2];
    const float* W1   = (const float*)d_in[3];
    const float* b1   = (const float*)d_in[4];
    const float* W2   = (const float*)d_in[5];
    const float* b2   = (const float*)d_in[6];
    const float* Wout = (const float*)d_in[7];
    const float* bout = (const float*)d_in[8];
    float* out = (float*)d_out;

    unsigned char* base = nullptr;
    cudaGetSymbolAddress((void**)&base, g_scratch);

    float* cur0 = (float*)(base + OFF_CUR0);
    float* c0   = (float*)(base + OFF_C0);
    float* cur1 = (float*)(base + OFF_CUR1);
    float* c1   = (float*)(base + OFF_C1);
    float* cur2 = (float*)(base + OFF_CUR2);
    float* c2   = (float*)(base + OFF_C2);
    float* cur3 = (float*)(base + OFF_CUR3);
    float* c3   = (float*)(base + OFF_C3);
    float* cur4 = (float*)(base + OFF_CUR4);

    // 1) cur0 = x @ W0 (25600x2048x1024): PURE CHAIN (no fold)
    gemm2_kernel<128, false>
        <<<dim3(DH0 / 64, (BSZ * TT) / 128), 256>>>(
            x, W0, cur0, BSZ * TT, DH0, DIN, DIN);
    // 2) LIF layer 0 -> s0 + counts
    lif_seq_kernel<<<(BSZ * DH0 + 255) / 256, 256>>>(cur0, b0, out + S0_OFF,
                                                     c0, BSZ, DH0);
    // 3) cur1 = c0 @ W1 (512x1024x2048): panels KC=512, left-fold
    gemm2_kernel<64, true>
        <<<dim3(DH1 / 64, BSZ / 64), 128>>>(c0, W1, cur1, BSZ, DH1, DH0, 512);
    lif_const_kernel<true><<<(BSZ * DH1 + 255) / 256, 256>>>(
        cur1, b1, out + S1_OFF, c1, BSZ, DH1);
    // 4) cur2 = c1 @ W2 (512x1024x1024): panels KC=512
    gemm2_kernel<64, true>
        <<<dim3(DOUTD / 64, BSZ / 64), 128>>>(c1, W2, cur2, BSZ, DOUTD, DH1,
                                              512);
    lif_const_kernel<true><<<(BSZ * DOUTD + 255) / 256, 256>>>(
        cur2, b2, out + S2_OFF, c2, BSZ, DOUTD);
    // 5) cur3 = c2 @ W2 again: panels KC=512
    gemm2_kernel<64, true>
        <<<dim3(DOUTD / 64, BSZ / 64), 128>>>(c2, W2, cur3, BSZ, DOUTD, DH1,
                                              512);
    lif_const_kernel<false><<<(BSZ * DOUTD + 255) / 256, 256>>>(
        cur3, b2, nullptr, c3, BSZ, DOUTD);
    // 6) out = c3 @ Wout + bout: panels KC=512
    gemm2_kernel<64, true>
        <<<dim3(DOUTD / 64, BSZ / 64), 128>>>(c3, Wout, cur4, BSZ, DOUTD,
                                              DOUTD, 512);
    final_out_kernel<<<(BSZ * DOUTD + 255) / 256, 256>>>(cur4, bout,
                                                         out + OUT_OFF);
}